// round 10
// baseline (speedup 1.0000x reference)
#include <cuda_runtime.h>
#include <cstdint>

// PointPillars scatter, inverted as index-map + gather (PDL-chained).
// B=4, C=64, H=512, W=512, P read from in_sizes.
//
// Init-free map: g_map holds (pid+1), 0 = empty. Zero-initialized at module
// load; gather self-cleans consumed cells so every graph replay starts from
// a clean map (gather -> next-replay scatter is stream-ordered).
//
// Round-9 diagnosis: gather was LSU-issue-bound (64 STG.32 per warp-cell),
// not DRAM-bound (DRAM/L2/L1 all <=65%). This version gives each thread 4
// consecutive cells and does a 4x4 register transpose per 16-channel chunk
// so every output store is an STG.128 (warp => 512B contiguous). LSU ops
// drop from 2.5/cell to 1/cell. No smem, no __syncthreads (round-7 lesson:
// barriers after random gathers collapse MLP).
#define B_ 4
#define C_ 64
#define H_ 512
#define W_ 512
#define HW_ (H_ * W_)        // 262144 = 2^18
#define BHW_ (B_ * HW_)      // 1048576

__device__ int g_map[BHW_];  // zero-initialized at load; 0 = empty

// ---------------------------------------------------------------------------
// Kernel 1: scatter (pid+1) per pillar. atomicMax => highest pillar index
// wins == the reference's sequential last-write-wins.
__global__ void __launch_bounds__(512) k_scatter_idx(const int* __restrict__ coords, int P) {
    int p = blockIdx.x * blockDim.x + threadIdx.x;
    if (p < P) {
        int4 c = __ldcs(reinterpret_cast<const int4*>(coords) + p);  // [b,z,y,x]
        int b = c.x, y = c.z, x = c.w;
        if ((unsigned)y < H_ && (unsigned)x < W_) {
            atomicMax(&g_map[(b * H_ + y) * W_ + x], p + 1);
        }
    }
    cudaTriggerProgrammaticLaunchCompletion();
}

// ---------------------------------------------------------------------------
// float4 component by compile-time-unrolled index (folds to .x/.y/.z/.w).
__device__ __forceinline__ float f4c(const float4& v, int j) {
    return j == 0 ? v.x : (j == 1 ? v.y : (j == 2 ? v.z : v.w));
}

// Kernel 2: gather + self-clean. Thread owns 4 consecutive cells; loops over
// four 16-channel chunks. Per chunk: 16 LDG.128 (4 per occupied cell, 64B
// contiguous slice of its feature row) -> 4x4 register transpose -> 16
// STG.128 (each warp store = 512B contiguous along sp, streaming).
__global__ void __launch_bounds__(256) k_gather(const float* __restrict__ feat,
                                                float* __restrict__ out) {
    int t = blockIdx.x * blockDim.x + threadIdx.x;   // cell-group id
    int s = t * 4;                                   // first of 4 cells
    int b  = s >> 18;
    int sp = s & (HW_ - 1);

    cudaGridDependencySynchronize();   // scatter grid fully complete

    int4 m = *reinterpret_cast<int4*>(&g_map[s]);    // 4 map entries, aligned
    if (m.x | m.y | m.z | m.w)
        *reinterpret_cast<int4*>(&g_map[s]) = make_int4(0, 0, 0, 0);  // self-clean

    const int pid[4] = { m.x, m.y, m.z, m.w };
    float* opb = out + (size_t)b * (C_ * HW_) + sp;

#pragma unroll
    for (int ch = 0; ch < 4; ch++) {                 // 16-channel chunk
        float4 v[4][4];                              // [cell][quad-of-4-channels]
#pragma unroll
        for (int cell = 0; cell < 4; cell++) {
            if (pid[cell] > 0) {
                const float4* fp = reinterpret_cast<const float4*>(feat)
                                 + (size_t)(pid[cell] - 1) * 16 + ch * 4;
#pragma unroll
                for (int q = 0; q < 4; q++) v[cell][q] = fp[q];
            } else {
#pragma unroll
                for (int q = 0; q < 4; q++) v[cell][q] = make_float4(0.f, 0.f, 0.f, 0.f);
            }
        }
        // Transpose: for each channel in the chunk, pack the 4 cells' values
        // into one float4 and store 16B at [c*HW_ + sp].
#pragma unroll
        for (int q = 0; q < 4; q++) {
#pragma unroll
            for (int j = 0; j < 4; j++) {
                int c = ch * 16 + q * 4 + j;
                float4 w = make_float4(f4c(v[0][q], j), f4c(v[1][q], j),
                                       f4c(v[2][q], j), f4c(v[3][q], j));
                __stcs(reinterpret_cast<float4*>(opb + (size_t)c * HW_), w);
            }
        }
    }
}

// ---------------------------------------------------------------------------
extern "C" void kernel_launch(void* const* d_in, const int* in_sizes, int n_in,
                              void* d_out, int out_size) {
    const float* feat   = (const float*)d_in[0];   // [P, C] float32
    const int*   coords = (const int*)d_in[1];     // [P, 4] int32
    int P = in_sizes[1] / 4;

    k_scatter_idx<<<(P + 511) / 512, 512>>>(coords, P);

    // Gather with programmatic dependent launch on the scatter.
    cudaLaunchConfig_t cfg = {};
    cfg.gridDim  = dim3(BHW_ / 4 / 256);
    cfg.blockDim = dim3(256);
    cfg.stream   = 0;  // capture stream
    cudaLaunchAttribute attr[1];
    attr[0].id = cudaLaunchAttributeProgrammaticStreamSerialization;
    attr[0].val.programmaticStreamSerializationAllowed = 1;
    cfg.attrs    = attr;
    cfg.numAttrs = 1;
    cudaLaunchKernelEx(&cfg, k_gather, feat, (float*)d_out);
}

// round 11
// speedup vs baseline: 1.0032x; 1.0032x over previous
#include <cuda_runtime.h>
#include <cstdint>

// PointPillars scatter, inverted as index-map + gather, FUSED into one
// persistent kernel with a software grid barrier between the phases.
// B=4, C=64, H=512, W=512, P read from in_sizes.
//
// Init-free map: g_map holds (pid+1), 0 = empty. Zero-initialized at module
// load; phase 2 self-cleans consumed cells so every graph replay starts
// from a clean map.
//
// Replay-safe grid barrier: g_bar increases monotonically; each replay adds
// exactly NBLK_ arrivals, and every block waits until the counter reaches
// the next multiple of NBLK_. No reset, identical work every call.
// Co-residency: 296 blocks x 256 threads at ~74 regs -> >=3 blocks/SM
// occupancy limit, so the whole grid is resident in wave 1 (no deadlock).
//
// Measured invariants (rounds 5-10): the gather phase runs at ~59-60us /
// DRAM ~65% regardless of occupancy, cache policy, or store width -> it is
// at the mixed-stream DRAM floor. No smem, no __syncthreads between the
// random reads and the stores (round-7: barriers there collapse MLP).
#define B_ 4
#define C_ 64
#define H_ 512
#define W_ 512
#define HW_ (H_ * W_)        // 262144 = 2^18
#define BHW_ (B_ * HW_)      // 1048576

#define NBLK_ 296
#define NTHR_ 256
#define TOT_  (NBLK_ * NTHR_)   // 75776 threads

__device__ int g_map[BHW_];            // zero-initialized; 0 = empty
__device__ unsigned int g_bar = 0;     // monotonic grid-barrier counter

__global__ void __launch_bounds__(NTHR_) k_fused(const float* __restrict__ feat,
                                                 const int* __restrict__ coords,
                                                 float* __restrict__ out, int P) {
    const int gtid = blockIdx.x * NTHR_ + threadIdx.x;

    // ---------------- Phase 1: scatter (pid+1), last-write-wins ----------
    for (int p = gtid; p < P; p += TOT_) {
        int4 c = __ldcs(reinterpret_cast<const int4*>(coords) + p);  // [b,z,y,x]
        int b = c.x, y = c.z, x = c.w;
        if ((unsigned)y < H_ && (unsigned)x < W_) {
            atomicMax(&g_map[(b * H_ + y) * W_ + x], p + 1);
        }
    }

    // ---------------- Grid barrier (replay-safe, no reset) ---------------
    __syncthreads();                       // block's scatter work issued
    if (threadIdx.x == 0) {
        __threadfence();                   // publish atomics before arriving
        unsigned int my = atomicAdd(&g_bar, 1u);
        unsigned int target = (my / NBLK_ + 1u) * NBLK_;
        while (atomicAdd(&g_bar, 0u) < target) { __nanosleep(64); }
    }
    __syncthreads();
    __threadfence();                       // acquire: see all blocks' atomics

    // ---------------- Phase 2: gather + self-clean -----------------------
    for (int s = gtid; s < BHW_; s += TOT_) {
        int b  = s >> 18;                  // / HW_
        int sp = s & (HW_ - 1);

        int v = g_map[s];

        float4 r[16];
        if (v > 0) {
            g_map[s] = 0;                  // self-clean for next replay
            const float4* fp = reinterpret_cast<const float4*>(feat + (size_t)(v - 1) * C_);
#pragma unroll
            for (int i = 0; i < 16; i++) r[i] = __ldcs(fp + i);
        } else {
#pragma unroll
            for (int i = 0; i < 16; i++) r[i] = make_float4(0.f, 0.f, 0.f, 0.f);
        }

        float* op = out + (size_t)b * (C_ * HW_) + sp;
#pragma unroll
        for (int i = 0; i < 16; i++) {
            __stcs(op + (size_t)(4 * i + 0) * HW_, r[i].x);
            __stcs(op + (size_t)(4 * i + 1) * HW_, r[i].y);
            __stcs(op + (size_t)(4 * i + 2) * HW_, r[i].z);
            __stcs(op + (size_t)(4 * i + 3) * HW_, r[i].w);
        }
    }
}

// ---------------------------------------------------------------------------
extern "C" void kernel_launch(void* const* d_in, const int* in_sizes, int n_in,
                              void* d_out, int out_size) {
    const float* feat   = (const float*)d_in[0];   // [P, C] float32
    const int*   coords = (const int*)d_in[1];     // [P, 4] int32
    int P = in_sizes[1] / 4;

    k_fused<<<NBLK_, NTHR_>>>(feat, coords, (float*)d_out, P);
}

// round 12
// speedup vs baseline: 1.1000x; 1.0965x over previous
#include <cuda_runtime.h>
#include <cstdint>

// PointPillars scatter, inverted as index-map + gather (PDL-chained).
// B=4, C=64, H=512, W=512, P read from in_sizes.
//
// Init-free map: g_map holds (pid+1), 0 = empty. Zero-initialized at module
// load; gather self-cleans consumed cells so every graph replay starts from
// a clean map (gather -> next-replay scatter is stream-ordered).
//
// Evidence matrix (rounds 5-11): gather is ~59-60us at DRAM ~65% invariant
// to occupancy (30-89%), cache policy, store width, and thread mapping ->
// mixed-stream DRAM floor. Barriers between random reads and stores are
// catastrophic (r7); software grid-barrier fusion loses to PDL (r11).
// This round: round-9 gather verbatim + ILP-4 scatter (4 pillars/thread,
// front-batched loads, REDG.MAX atomics) to shrink the ~3us front-end.
#define B_ 4
#define C_ 64
#define H_ 512
#define W_ 512
#define HW_ (H_ * W_)        // 262144 = 2^18
#define BHW_ (B_ * HW_)      // 1048576

__device__ int g_map[BHW_];  // zero-initialized at load; 0 = empty

// ---------------------------------------------------------------------------
// Kernel 1: scatter (pid+1) per pillar, 4 pillars per thread with batched
// loads (MLP=4). atomicMax (result unused -> REDG.MAX) => highest pillar
// index wins == the reference's sequential last-write-wins.
__global__ void __launch_bounds__(256) k_scatter_idx(const int* __restrict__ coords, int P) {
    int p0 = (blockIdx.x * blockDim.x + threadIdx.x) * 4;
    const int4* cp = reinterpret_cast<const int4*>(coords);

    if (p0 + 3 < P) {
        int4 c0 = __ldcs(cp + p0 + 0);
        int4 c1 = __ldcs(cp + p0 + 1);
        int4 c2 = __ldcs(cp + p0 + 2);
        int4 c3 = __ldcs(cp + p0 + 3);
        if ((unsigned)c0.z < H_ && (unsigned)c0.w < W_)
            atomicMax(&g_map[(c0.x * H_ + c0.z) * W_ + c0.w], p0 + 1);
        if ((unsigned)c1.z < H_ && (unsigned)c1.w < W_)
            atomicMax(&g_map[(c1.x * H_ + c1.z) * W_ + c1.w], p0 + 2);
        if ((unsigned)c2.z < H_ && (unsigned)c2.w < W_)
            atomicMax(&g_map[(c2.x * H_ + c2.z) * W_ + c2.w], p0 + 3);
        if ((unsigned)c3.z < H_ && (unsigned)c3.w < W_)
            atomicMax(&g_map[(c3.x * H_ + c3.z) * W_ + c3.w], p0 + 4);
    } else {
        for (int p = p0; p < P; p++) {
            int4 c = __ldcs(cp + p);
            if ((unsigned)c.z < H_ && (unsigned)c.w < W_)
                atomicMax(&g_map[(c.x * H_ + c.z) * W_ + c.w], p + 1);
        }
    }
    cudaTriggerProgrammaticLaunchCompletion();
}

// ---------------------------------------------------------------------------
// Kernel 2: gather + self-clean (round-9 proven form). One thread per BEV
// cell owns all 64 channels: 16x float4 contiguous feature-row read
// (streaming), 64 strided channel stores coalesced across the warp in w
// (streaming). PDL: waits for the scatter grid only at the map read.
__global__ void __launch_bounds__(256) k_gather(const float* __restrict__ feat,
                                                float* __restrict__ out) {
    int s = blockIdx.x * blockDim.x + threadIdx.x;   // 0 .. BHW_-1
    int b  = s >> 18;            // / HW_
    int sp = s & (HW_ - 1);      // within-batch spatial index

    cudaGridDependencySynchronize();   // scatter grid fully complete

    int v = g_map[s];

    float4 r[16];
    if (v > 0) {
        g_map[s] = 0;            // self-clean for next graph replay
        const float4* fp = reinterpret_cast<const float4*>(feat + (size_t)(v - 1) * C_);
#pragma unroll
        for (int i = 0; i < 16; i++) r[i] = __ldcs(fp + i);
    } else {
#pragma unroll
        for (int i = 0; i < 16; i++) r[i] = make_float4(0.f, 0.f, 0.f, 0.f);
    }

    float* op = out + (size_t)b * (C_ * HW_) + sp;
#pragma unroll
    for (int i = 0; i < 16; i++) {
        __stcs(op + (size_t)(4 * i + 0) * HW_, r[i].x);
        __stcs(op + (size_t)(4 * i + 1) * HW_, r[i].y);
        __stcs(op + (size_t)(4 * i + 2) * HW_, r[i].z);
        __stcs(op + (size_t)(4 * i + 3) * HW_, r[i].w);
    }
}

// ---------------------------------------------------------------------------
extern "C" void kernel_launch(void* const* d_in, const int* in_sizes, int n_in,
                              void* d_out, int out_size) {
    const float* feat   = (const float*)d_in[0];   // [P, C] float32
    const int*   coords = (const int*)d_in[1];     // [P, 4] int32
    int P = in_sizes[1] / 4;

    int sthreads = (P + 3) / 4;
    k_scatter_idx<<<(sthreads + 255) / 256, 256>>>(coords, P);

    // Gather with programmatic dependent launch on the scatter.
    cudaLaunchConfig_t cfg = {};
    cfg.gridDim  = dim3(BHW_ / 256);
    cfg.blockDim = dim3(256);
    cfg.stream   = 0;  // capture stream
    cudaLaunchAttribute attr[1];
    attr[0].id = cudaLaunchAttributeProgrammaticStreamSerialization;
    attr[0].val.programmaticStreamSerializationAllowed = 1;
    cfg.attrs    = attr;
    cfg.numAttrs = 1;
    cudaLaunchKernelEx(&cfg, k_gather, feat, (float*)d_out);
}